// round 1
// baseline (speedup 1.0000x reference)
#include <cuda_runtime.h>
#include <math.h>

#define C_SEQ 1024
#define B_SZ  8
#define DIMN  1024
#define NH    16
#define HD    64
#define M_TOT (C_SEQ * B_SZ)   // 8192

// Scratch (static device allocations are allowed; cudaMalloc is not)
__device__ float g_Q[M_TOT * DIMN];
__device__ float g_K[M_TOT * DIMN];
__device__ float g_V[M_TOT * DIMN];
__device__ float g_AO[M_TOT * DIMN];

// ---------------------------------------------------------------------------
// SGEMM-NT body: C[m][n] = sum_k A[m][k] * W[n][k]
// M x N x K with M=8192, N=K=1024. 128x128 block tile, 16-deep k tile,
// 256 threads, 8x8 register micro-tile per thread.
// ---------------------------------------------------------------------------
__device__ __forceinline__ void gemm_body_nt(const float* __restrict__ A,
                                             const float* __restrict__ W,
                                             float* __restrict__ Cout) {
    const int K = DIMN, N = DIMN;
    __shared__ float As[16][132];   // pad 132: scatter stores & reads conflict-light
    __shared__ float Bs[16][132];

    const int t  = threadIdx.x;
    const int m0 = blockIdx.y * 128;
    const int n0 = blockIdx.x * 128;
    const int lr = t >> 2;          // 0..63  (load row)
    const int lc = (t & 3) << 2;    // 0,4,8,12 (load col, float4)
    const int ty = t >> 4;          // 0..15
    const int tx = t & 15;          // 0..15

    float acc[8][8];
#pragma unroll
    for (int i = 0; i < 8; ++i)
#pragma unroll
        for (int j = 0; j < 8; ++j) acc[i][j] = 0.f;

    const float* Aptr = A + (size_t)(m0 + lr) * K + lc;
    const float* Wptr = W + (size_t)(n0 + lr) * K + lc;

    for (int k0 = 0; k0 < K; k0 += 16) {
        float4 a0 = *(const float4*)(Aptr + k0);
        float4 a1 = *(const float4*)(Aptr + (size_t)64 * K + k0);
        float4 b0 = *(const float4*)(Wptr + k0);
        float4 b1 = *(const float4*)(Wptr + (size_t)64 * K + k0);
        __syncthreads();   // protect previous iteration's smem reads
        As[lc + 0][lr] = a0.x; As[lc + 1][lr] = a0.y;
        As[lc + 2][lr] = a0.z; As[lc + 3][lr] = a0.w;
        As[lc + 0][lr + 64] = a1.x; As[lc + 1][lr + 64] = a1.y;
        As[lc + 2][lr + 64] = a1.z; As[lc + 3][lr + 64] = a1.w;
        Bs[lc + 0][lr] = b0.x; Bs[lc + 1][lr] = b0.y;
        Bs[lc + 2][lr] = b0.z; Bs[lc + 3][lr] = b0.w;
        Bs[lc + 0][lr + 64] = b1.x; Bs[lc + 1][lr + 64] = b1.y;
        Bs[lc + 2][lr + 64] = b1.z; Bs[lc + 3][lr + 64] = b1.w;
        __syncthreads();

#pragma unroll
        for (int kk = 0; kk < 16; ++kk) {
            float a[8], b[8];
            *(float4*)&a[0] = *(float4*)&As[kk][ty * 8];
            *(float4*)&a[4] = *(float4*)&As[kk][ty * 8 + 4];
            *(float4*)&b[0] = *(float4*)&Bs[kk][tx * 8];
            *(float4*)&b[4] = *(float4*)&Bs[kk][tx * 8 + 4];
#pragma unroll
            for (int i = 0; i < 8; ++i)
#pragma unroll
                for (int j = 0; j < 8; ++j)
                    acc[i][j] = fmaf(a[i], b[j], acc[i][j]);
        }
    }

    float* Crow = Cout + n0 + tx * 8;
#pragma unroll
    for (int i = 0; i < 8; ++i) {
        float4 c0 = make_float4(acc[i][0], acc[i][1], acc[i][2], acc[i][3]);
        float4 c1 = make_float4(acc[i][4], acc[i][5], acc[i][6], acc[i][7]);
        size_t row = (size_t)(m0 + ty * 8 + i) * N;
        *(float4*)(Crow + row)     = c0;
        *(float4*)(Crow + row + 4) = c1;
    }
}

__global__ __launch_bounds__(256) void qkv_kernel(const float* __restrict__ h,
                                                  const float* __restrict__ Wq,
                                                  const float* __restrict__ Wk,
                                                  const float* __restrict__ Wv) {
    const float* W = (blockIdx.z == 0) ? Wq : (blockIdx.z == 1) ? Wk : Wv;
    float* out = (blockIdx.z == 0) ? g_Q : (blockIdx.z == 1) ? g_K : g_V;
    gemm_body_nt(h, W, out);
}

__global__ __launch_bounds__(256) void proj_kernel(const float* __restrict__ Wo,
                                                   float* __restrict__ out) {
    gemm_body_nt(g_AO, Wo, out);
}

// ---------------------------------------------------------------------------
// Fused attention: per block = (64-query tile, one (head, batch) pair).
// Online softmax (flash-style). 256 threads = 64 queries x 4 lanes.
// Each lane owns a 16-wide slice of head_dim for the output accumulator
// and an 8-wide slice of each 32-key tile for the scores.
// ---------------------------------------------------------------------------
#define BQ  64
#define BKT 32

__global__ __launch_bounds__(256) void attn_kernel(const float* __restrict__ log_beta) {
    __shared__ float sQ[BQ][68];
    __shared__ float sK[BKT][68];
    __shared__ float sV[BKT][68];

    const int t    = threadIdx.x;
    const int qt   = blockIdx.x;     // 0..15 query tiles
    const int hb   = blockIdx.y;     // 0..127 (head, batch)
    const int hh   = hb >> 3;
    const int bb   = hb & 7;
    const float beta = expf(log_beta[hh]);
    const int q    = t >> 2;         // 0..63
    const int dq   = t & 3;          // 0..3
    const int d0   = dq << 4;        // head_dim slice base
    const int lane = t & 31;

    // Load Q tile (64 x 64)
    {
        const int r = t >> 2;
        const int c = (t & 3) << 4;
        const float* src = g_Q + (size_t)((qt * BQ + r) * B_SZ + bb) * DIMN + hh * HD + c;
#pragma unroll
        for (int j = 0; j < 4; ++j)
            *(float4*)&sQ[r][c + j * 4] = *(const float4*)(src + j * 4);
    }

    float acc[16];
#pragma unroll
    for (int i = 0; i < 16; ++i) acc[i] = 0.f;
    float mrow = -1e30f, lrow = 0.f;

    const int kvr = t >> 3;          // 0..31
    const int kvc = (t & 7) << 3;    // 0..56
    const float* ksrc = g_K + (size_t)(kvr * B_SZ + bb) * DIMN + hh * HD + kvc;
    const float* vsrc = g_V + (size_t)(kvr * B_SZ + bb) * DIMN + hh * HD + kvc;

    for (int k0 = 0; k0 < C_SEQ; k0 += BKT) {
        __syncthreads();             // previous tile fully consumed
        size_t off = (size_t)k0 * B_SZ * DIMN;
        *(float4*)&sK[kvr][kvc]     = *(const float4*)(ksrc + off);
        *(float4*)&sK[kvr][kvc + 4] = *(const float4*)(ksrc + off + 4);
        *(float4*)&sV[kvr][kvc]     = *(const float4*)(vsrc + off);
        *(float4*)&sV[kvr][kvc + 4] = *(const float4*)(vsrc + off + 4);
        __syncthreads();

        // Scores: this lane computes keys kk = dq*8 + j, j in [0,8)
        float s[8];
#pragma unroll
        for (int j = 0; j < 8; ++j) s[j] = 0.f;
#pragma unroll
        for (int d4 = 0; d4 < 16; ++d4) {
            float4 qv = *(float4*)&sQ[q][d4 * 4];
#pragma unroll
            for (int j = 0; j < 8; ++j) {
                float4 kv = *(float4*)&sK[dq * 8 + j][d4 * 4];
                s[j] = fmaf(qv.x, kv.x, s[j]);
                s[j] = fmaf(qv.y, kv.y, s[j]);
                s[j] = fmaf(qv.z, kv.z, s[j]);
                s[j] = fmaf(qv.w, kv.w, s[j]);
            }
        }
#pragma unroll
        for (int j = 0; j < 8; ++j) s[j] *= beta;

        // Online softmax update within the 4-lane query group
        float mt = s[0];
#pragma unroll
        for (int j = 1; j < 8; ++j) mt = fmaxf(mt, s[j]);
        mt = fmaxf(mt, __shfl_xor_sync(0xffffffffu, mt, 1));
        mt = fmaxf(mt, __shfl_xor_sync(0xffffffffu, mt, 2));
        float mnew  = fmaxf(mrow, mt);
        float scale = __expf(mrow - mnew);
        float p[8], lsum = 0.f;
#pragma unroll
        for (int j = 0; j < 8; ++j) { p[j] = __expf(s[j] - mnew); lsum += p[j]; }
        lsum += __shfl_xor_sync(0xffffffffu, lsum, 1);
        lsum += __shfl_xor_sync(0xffffffffu, lsum, 2);
        lrow = lrow * scale + lsum;
        mrow = mnew;
#pragma unroll
        for (int i = 0; i < 16; ++i) acc[i] *= scale;

        // PV: broadcast p across the 4-lane group, accumulate this lane's dims
        const int base = lane & ~3;
#pragma unroll
        for (int src = 0; src < 4; ++src) {
#pragma unroll
            for (int j = 0; j < 8; ++j) {
                float pk = __shfl_sync(0xffffffffu, p[j], base + src);
                int kk = src * 8 + j;
#pragma unroll
                for (int i4 = 0; i4 < 4; ++i4) {
                    float4 vv = *(float4*)&sV[kk][d0 + i4 * 4];
                    acc[i4 * 4 + 0] = fmaf(pk, vv.x, acc[i4 * 4 + 0]);
                    acc[i4 * 4 + 1] = fmaf(pk, vv.y, acc[i4 * 4 + 1]);
                    acc[i4 * 4 + 2] = fmaf(pk, vv.z, acc[i4 * 4 + 2]);
                    acc[i4 * 4 + 3] = fmaf(pk, vv.w, acc[i4 * 4 + 3]);
                }
            }
        }
    }

    float inv = 1.f / lrow;
    float* dst = g_AO + (size_t)((qt * BQ + q) * B_SZ + bb) * DIMN + hh * HD + d0;
#pragma unroll
    for (int i4 = 0; i4 < 4; ++i4) {
        float4 o = make_float4(acc[i4 * 4 + 0] * inv, acc[i4 * 4 + 1] * inv,
                               acc[i4 * 4 + 2] * inv, acc[i4 * 4 + 3] * inv);
        *(float4*)(dst + i4 * 4) = o;
    }
}

// ---------------------------------------------------------------------------
// Bias + LayerNorm, in-place on d_out. One block per row, 256 threads x 4.
// ---------------------------------------------------------------------------
__global__ __launch_bounds__(256) void ln_kernel(const float* __restrict__ b_o,
                                                 const float* __restrict__ gamma,
                                                 const float* __restrict__ lbeta,
                                                 float* __restrict__ io) {
    __shared__ float red[16];
    const int row = blockIdx.x;
    const int t   = threadIdx.x;
    float* x = io + (size_t)row * DIMN;

    float4 xv = *(float4*)&x[t * 4];
    float4 bv = *(const float4*)&b_o[t * 4];
    xv.x += bv.x; xv.y += bv.y; xv.z += bv.z; xv.w += bv.w;

    float s  = xv.x + xv.y + xv.z + xv.w;
    float ss = xv.x * xv.x + xv.y * xv.y + xv.z * xv.z + xv.w * xv.w;
#pragma unroll
    for (int o = 16; o; o >>= 1) {
        s  += __shfl_xor_sync(0xffffffffu, s, o);
        ss += __shfl_xor_sync(0xffffffffu, ss, o);
    }
    if ((t & 31) == 0) { red[t >> 5] = s; red[8 + (t >> 5)] = ss; }
    __syncthreads();
    float stot = 0.f, sstot = 0.f;
#pragma unroll
    for (int w = 0; w < 8; ++w) { stot += red[w]; sstot += red[8 + w]; }

    const float mean = stot * (1.f / DIMN);
    const float var  = sstot * (1.f / DIMN) - mean * mean;
    const float rstd = rsqrtf(var + 1e-5f);

    float4 gv = *(const float4*)&gamma[t * 4];
    float4 ev = *(const float4*)&lbeta[t * 4];
    float4 o;
    o.x = (xv.x - mean) * rstd * gv.x + ev.x;
    o.y = (xv.y - mean) * rstd * gv.y + ev.y;
    o.z = (xv.z - mean) * rstd * gv.z + ev.z;
    o.w = (xv.w - mean) * rstd * gv.w + ev.w;
    *(float4*)&x[t * 4] = o;
}

// ---------------------------------------------------------------------------
extern "C" void kernel_launch(void* const* d_in, const int* in_sizes, int n_in,
                              void* d_out, int out_size) {
    const float* h        = (const float*)d_in[0];
    const float* Wq       = (const float*)d_in[1];
    const float* Wk       = (const float*)d_in[2];
    const float* Wv       = (const float*)d_in[3];
    const float* Wo       = (const float*)d_in[4];
    const float* b_o      = (const float*)d_in[5];
    const float* log_beta = (const float*)d_in[6];
    const float* gamma    = (const float*)d_in[7];
    const float* lbeta    = (const float*)d_in[8];
    float* out = (float*)d_out;

    qkv_kernel<<<dim3(DIMN / 128, M_TOT / 128, 3), 256>>>(h, Wq, Wk, Wv);
    attn_kernel<<<dim3(C_SEQ / BQ, NH * B_SZ), 256>>>(log_beta);
    proj_kernel<<<dim3(DIMN / 128, M_TOT / 128), 256>>>(Wo, out);
    ln_kernel<<<M_TOT, 256>>>(b_o, gamma, lbeta, out);
}

// round 3
// speedup vs baseline: 1.0514x; 1.0514x over previous
#include <cuda_runtime.h>
#include <math.h>
#include <stdint.h>

#define C_SEQ 1024
#define B_SZ  8
#define DIMN  1024
#define NH    16
#define HD    64
#define M_TOT (C_SEQ * B_SZ)   // 8192

// Scratch (static device allocations are allowed; cudaMalloc is not)
__device__ float g_Q[M_TOT * DIMN];
__device__ float g_K[M_TOT * DIMN];
__device__ float g_V[M_TOT * DIMN];
__device__ float g_AO[M_TOT * DIMN];

// ---------------------------------------------------------------------------
// 3xTF32 tensor-core GEMM-NT: C[m][n] = sum_k A[m][k] * W[n][k]
// Block 128x128, k-tile 32, 256 threads = 8 warps (2m x 4n), warp tile 64x32.
// Each warp: 4x4 grid of m16n8k8 mma tiles. 3xTF32 split for fp32 accuracy.
// ---------------------------------------------------------------------------

__device__ __forceinline__ uint32_t f2tf32(float x) {
    uint32_t r;
    asm("cvt.rna.tf32.f32 %0, %1;" : "=r"(r) : "f"(x));
    return r;
}

__device__ __forceinline__ void mma_tf32(float* c, const uint32_t* a, const uint32_t* b) {
    asm volatile(
        "mma.sync.aligned.m16n8k8.row.col.f32.tf32.tf32.f32 "
        "{%0,%1,%2,%3}, {%4,%5,%6,%7}, {%8,%9}, {%0,%1,%2,%3};"
        : "+f"(c[0]), "+f"(c[1]), "+f"(c[2]), "+f"(c[3])
        : "r"(a[0]), "r"(a[1]), "r"(a[2]), "r"(a[3]), "r"(b[0]), "r"(b[1]));
}

#define SPAD 36   // smem row stride (floats): bank = 4*g + tg -> conflict-free frags

__device__ __forceinline__ void gemm3x_body(const float* __restrict__ A,
                                            const float* __restrict__ W,
                                            float* __restrict__ Cout) {
    const int K = DIMN, N = DIMN;
    __shared__ float As[128][SPAD];
    __shared__ float Bs[128][SPAD];

    const int t    = threadIdx.x;
    const int warp = t >> 5;
    const int lane = t & 31;
    const int wm   = warp >> 2;      // 0..1
    const int wn   = warp & 3;       // 0..3
    const int g    = lane >> 2;      // 0..7
    const int tg   = lane & 3;       // 0..3

    const int m0 = blockIdx.y * 128;
    const int n0 = blockIdx.x * 128;

    float acc[4][4][4];
#pragma unroll
    for (int i = 0; i < 4; ++i)
#pragma unroll
        for (int j = 0; j < 4; ++j)
#pragma unroll
            for (int r = 0; r < 4; ++r) acc[i][j][r] = 0.f;

    // Global load mapping: 1024 float4 per matrix per k-tile, 4 per thread.
    // idx = t + 256*jj -> row = idx>>3 (0..127), c4 = idx&7 (float4 col)
    const int lrow = t >> 3;          // base row for jj=0; rows step by 32
    const int lc4  = (t & 7) * 4;     // float col

    const float* Aptr = A + (size_t)(m0 + lrow) * K + lc4;
    const float* Wptr = W + (size_t)(n0 + lrow) * K + lc4;

    float4 pa[4], pb[4];
#pragma unroll
    for (int jj = 0; jj < 4; ++jj) {
        pa[jj] = *(const float4*)(Aptr + (size_t)(jj * 32) * K);
        pb[jj] = *(const float4*)(Wptr + (size_t)(jj * 32) * K);
    }

    for (int kt = 0; kt < K / 32; ++kt) {
        __syncthreads();   // previous tile fully consumed
#pragma unroll
        for (int jj = 0; jj < 4; ++jj) {
            *(float4*)&As[lrow + jj * 32][lc4] = pa[jj];
            *(float4*)&Bs[lrow + jj * 32][lc4] = pb[jj];
        }
        __syncthreads();

        if (kt + 1 < K / 32) {
            const int k0 = (kt + 1) * 32;
#pragma unroll
            for (int jj = 0; jj < 4; ++jj) {
                pa[jj] = *(const float4*)(Aptr + (size_t)(jj * 32) * K + k0);
                pb[jj] = *(const float4*)(Wptr + (size_t)(jj * 32) * K + k0);
            }
        }

#pragma unroll
        for (int ks = 0; ks < 4; ++ks) {
            const int kb = ks * 8;
            // A fragments: 4 m-tiles, split into big/small tf32
            uint32_t ab[4][4], as[4][4];
#pragma unroll
            for (int i = 0; i < 4; ++i) {
                const int r0 = wm * 64 + i * 16 + g;
                float a0 = As[r0][kb + tg];
                float a1 = As[r0 + 8][kb + tg];
                float a2 = As[r0][kb + tg + 4];
                float a3 = As[r0 + 8][kb + tg + 4];
                ab[i][0] = f2tf32(a0); as[i][0] = f2tf32(a0 - __uint_as_float(ab[i][0]));
                ab[i][1] = f2tf32(a1); as[i][1] = f2tf32(a1 - __uint_as_float(ab[i][1]));
                ab[i][2] = f2tf32(a2); as[i][2] = f2tf32(a2 - __uint_as_float(ab[i][2]));
                ab[i][3] = f2tf32(a3); as[i][3] = f2tf32(a3 - __uint_as_float(ab[i][3]));
            }
            // B fragments: 4 n-tiles
            uint32_t bb[4][2], bs[4][2];
#pragma unroll
            for (int j = 0; j < 4; ++j) {
                const int n = wn * 32 + j * 8 + g;
                float b0 = Bs[n][kb + tg];
                float b1 = Bs[n][kb + tg + 4];
                bb[j][0] = f2tf32(b0); bs[j][0] = f2tf32(b0 - __uint_as_float(bb[j][0]));
                bb[j][1] = f2tf32(b1); bs[j][1] = f2tf32(b1 - __uint_as_float(bb[j][1]));
            }
            // 3 passes: big*big, big*small, small*big (16 independent mma each)
#pragma unroll
            for (int j = 0; j < 4; ++j)
#pragma unroll
                for (int i = 0; i < 4; ++i) mma_tf32(acc[i][j], ab[i], bb[j]);
#pragma unroll
            for (int j = 0; j < 4; ++j)
#pragma unroll
                for (int i = 0; i < 4; ++i) mma_tf32(acc[i][j], ab[i], bs[j]);
#pragma unroll
            for (int j = 0; j < 4; ++j)
#pragma unroll
                for (int i = 0; i < 4; ++i) mma_tf32(acc[i][j], as[i], bb[j]);
        }
    }

    // Epilogue: c0,c1 at (row, 2tg), c2,c3 at (row+8, 2tg)
#pragma unroll
    for (int i = 0; i < 4; ++i) {
        const int row = m0 + wm * 64 + i * 16 + g;
#pragma unroll
        for (int j = 0; j < 4; ++j) {
            const int col = n0 + wn * 32 + j * 8 + tg * 2;
            float2 lo = make_float2(acc[i][j][0], acc[i][j][1]);
            float2 hi = make_float2(acc[i][j][2], acc[i][j][3]);
            *(float2*)(Cout + (size_t)row * N + col)       = lo;
            *(float2*)(Cout + (size_t)(row + 8) * N + col) = hi;
        }
    }
}

__global__ __launch_bounds__(256) void qkv_kernel(const float* __restrict__ h,
                                                  const float* __restrict__ Wq,
                                                  const float* __restrict__ Wk,
                                                  const float* __restrict__ Wv) {
    const float* W = (blockIdx.z == 0) ? Wq : (blockIdx.z == 1) ? Wk : Wv;
    float* out = (blockIdx.z == 0) ? g_Q : (blockIdx.z == 1) ? g_K : g_V;
    gemm3x_body(h, W, out);
}

__global__ __launch_bounds__(256) void proj_kernel(const float* __restrict__ Wo,
                                                   float* __restrict__ out) {
    gemm3x_body(g_AO, Wo, out);
}

// ---------------------------------------------------------------------------
// Fused attention (unchanged this round): flash-style online softmax.
// Block = (64-query tile, one (head,batch)). 256 threads = 64 q x 4 lanes.
// ---------------------------------------------------------------------------
#define BQ  64
#define BKT 32

__global__ __launch_bounds__(256) void attn_kernel(const float* __restrict__ log_beta) {
    __shared__ float sQ[BQ][68];
    __shared__ float sK[BKT][68];
    __shared__ float sV[BKT][68];

    const int t    = threadIdx.x;
    const int qt   = blockIdx.x;
    const int hb   = blockIdx.y;
    const int hh   = hb >> 3;
    const int bb   = hb & 7;
    const float beta = expf(log_beta[hh]);
    const int q    = t >> 2;
    const int dq   = t & 3;
    const int d0   = dq << 4;
    const int lane = t & 31;

    {
        const int r = t >> 2;
        const int c = (t & 3) << 4;
        const float* src = g_Q + (size_t)((qt * BQ + r) * B_SZ + bb) * DIMN + hh * HD + c;
#pragma unroll
        for (int j = 0; j < 4; ++j)
            *(float4*)&sQ[r][c + j * 4] = *(const float4*)(src + j * 4);
    }

    float acc[16];
#pragma unroll
    for (int i = 0; i < 16; ++i) acc[i] = 0.f;
    float mrow = -1e30f, lrow = 0.f;

    const int kvr = t >> 3;
    const int kvc = (t & 7) << 3;
    const float* ksrc = g_K + (size_t)(kvr * B_SZ + bb) * DIMN + hh * HD + kvc;
    const float* vsrc = g_V + (size_t)(kvr * B_SZ + bb) * DIMN + hh * HD + kvc;

    for (int k0 = 0; k0 < C_SEQ; k0 += BKT) {
        __syncthreads();
        size_t off = (size_t)k0 * B_SZ * DIMN;
        *(float4*)&sK[kvr][kvc]     = *(const float4*)(ksrc + off);
        *(float4*)&sK[kvr][kvc + 4] = *(const float4*)(ksrc + off + 4);
        *(float4*)&sV[kvr][kvc]     = *(const float4*)(vsrc + off);
        *(float4*)&sV[kvr][kvc + 4] = *(const float4*)(vsrc + off + 4);
        __syncthreads();

        float s[8];
#pragma unroll
        for (int j = 0; j < 8; ++j) s[j] = 0.f;
#pragma unroll
        for (int d4 = 0; d4 < 16; ++d4) {
            float4 qv = *(float4*)&sQ[q][d4 * 4];
#pragma unroll
            for (int j = 0; j < 8; ++j) {
                float4 kv = *(float4*)&sK[dq * 8 + j][d4 * 4];
                s[j] = fmaf(qv.x, kv.x, s[j]);
                s[j] = fmaf(qv.y, kv.y, s[j]);
                s[j] = fmaf(qv.z, kv.z, s[j]);
                s[j] = fmaf(qv.w, kv.w, s[j]);
            }
        }
#pragma unroll
        for (int j = 0; j < 8; ++j) s[j] *= beta;

        float mt = s[0];
#pragma unroll
        for (int j = 1; j < 8; ++j) mt = fmaxf(mt, s[j]);
        mt = fmaxf(mt, __shfl_xor_sync(0xffffffffu, mt, 1));
        mt = fmaxf(mt, __shfl_xor_sync(0xffffffffu, mt, 2));
        float mnew  = fmaxf(mrow, mt);
        float scale = __expf(mrow - mnew);
        float p[8], lsum = 0.f;
#pragma unroll
        for (int j = 0; j < 8; ++j) { p[j] = __expf(s[j] - mnew); lsum += p[j]; }
        lsum += __shfl_xor_sync(0xffffffffu, lsum, 1);
        lsum += __shfl_xor_sync(0xffffffffu, lsum, 2);
        lrow = lrow * scale + lsum;
        mrow = mnew;
#pragma unroll
        for (int i = 0; i < 16; ++i) acc[i] *= scale;

        const int base = lane & ~3;
#pragma unroll
        for (int src = 0; src < 4; ++src) {
#pragma unroll
            for (int j = 0; j < 8; ++j) {
                float pk = __shfl_sync(0xffffffffu, p[j], base + src);
                int kk = src * 8 + j;
#pragma unroll
                for (int i4 = 0; i4 < 4; ++i4) {
                    float4 vv = *(float4*)&sV[kk][d0 + i4 * 4];
                    acc[i4 * 4 + 0] = fmaf(pk, vv.x, acc[i4 * 4 + 0]);
                    acc[i4 * 4 + 1] = fmaf(pk, vv.y, acc[i4 * 4 + 1]);
                    acc[i4 * 4 + 2] = fmaf(pk, vv.z, acc[i4 * 4 + 2]);
                    acc[i4 * 4 + 3] = fmaf(pk, vv.w, acc[i4 * 4 + 3]);
                }
            }
        }
    }

    float inv = 1.f / lrow;
    float* dst = g_AO + (size_t)((qt * BQ + q) * B_SZ + bb) * DIMN + hh * HD + d0;
#pragma unroll
    for (int i4 = 0; i4 < 4; ++i4) {
        float4 o = make_float4(acc[i4 * 4 + 0] * inv, acc[i4 * 4 + 1] * inv,
                               acc[i4 * 4 + 2] * inv, acc[i4 * 4 + 3] * inv);
        *(float4*)(dst + i4 * 4) = o;
    }
}

// ---------------------------------------------------------------------------
// Bias + LayerNorm, in-place on d_out.
// ---------------------------------------------------------------------------
__global__ __launch_bounds__(256) void ln_kernel(const float* __restrict__ b_o,
                                                 const float* __restrict__ gamma,
                                                 const float* __restrict__ lbeta,
                                                 float* __restrict__ io) {
    __shared__ float red[16];
    const int row = blockIdx.x;
    const int t   = threadIdx.x;
    float* x = io + (size_t)row * DIMN;

    float4 xv = *(float4*)&x[t * 4];
    float4 bv = *(const float4*)&b_o[t * 4];
    xv.x += bv.x; xv.y += bv.y; xv.z += bv.z; xv.w += bv.w;

    float s  = xv.x + xv.y + xv.z + xv.w;
    float ss = xv.x * xv.x + xv.y * xv.y + xv.z * xv.z + xv.w * xv.w;
#pragma unroll
    for (int o = 16; o; o >>= 1) {
        s  += __shfl_xor_sync(0xffffffffu, s, o);
        ss += __shfl_xor_sync(0xffffffffu, ss, o);
    }
    if ((t & 31) == 0) { red[t >> 5] = s; red[8 + (t >> 5)] = ss; }
    __syncthreads();
    float stot = 0.f, sstot = 0.f;
#pragma unroll
    for (int w = 0; w < 8; ++w) { stot += red[w]; sstot += red[8 + w]; }

    const float mean = stot * (1.f / DIMN);
    const float var  = sstot * (1.f / DIMN) - mean * mean;
    const float rstd = rsqrtf(var + 1e-5f);

    float4 gv = *(const float4*)&gamma[t * 4];
    float4 ev = *(const float4*)&lbeta[t * 4];
    float4 o;
    o.x = (xv.x - mean) * rstd * gv.x + ev.x;
    o.y = (xv.y - mean) * rstd * gv.y + ev.y;
    o.z = (xv.z - mean) * rstd * gv.z + ev.z;
    o.w = (xv.w - mean) * rstd * gv.w + ev.w;
    *(float4*)&x[t * 4] = o;
}

// ---------------------------------------------------------------------------
extern "C" void kernel_launch(void* const* d_in, const int* in_sizes, int n_in,
                              void* d_out, int out_size) {
    const float* h        = (const float*)d_in[0];
    const float* Wq       = (const float*)d_in[1];
    const float* Wk       = (const float*)d_in[2];
    const float* Wv       = (const float*)d_in[3];
    const float* Wo       = (const float*)d_in[4];
    const float* b_o      = (const float*)d_in[5];
    const float* log_beta = (const float*)d_in[6];
    const float* gamma    = (const float*)d_in[7];
    const float* lbeta    = (const float*)d_in[8];
    float* out = (float*)d_out;

    qkv_kernel<<<dim3(DIMN / 128, M_TOT / 128, 3), 256>>>(h, Wq, Wk, Wv);
    attn_kernel<<<dim3(C_SEQ / BQ, NH * B_SZ), 256>>>(log_beta);
    proj_kernel<<<dim3(DIMN / 128, M_TOT / 128), 256>>>(Wo, out);
    ln_kernel<<<M_TOT, 256>>>(b_o, gamma, lbeta, out);
}

// round 4
// speedup vs baseline: 1.1534x; 1.0970x over previous
#include <cuda_runtime.h>
#include <cuda_bf16.h>
#include <math.h>
#include <stdint.h>

#define C_SEQ 1024
#define B_SZ  8
#define DIMN  1024
#define NH    16
#define HD    64
#define M_TOT (C_SEQ * B_SZ)   // 8192

// fp32 scratch
__device__ float g_Q[M_TOT * DIMN];
__device__ float g_K[M_TOT * DIMN];
__device__ float g_V[M_TOT * DIMN];
__device__ float g_AO[M_TOT * DIMN];
// bf16 split planes
__device__ __nv_bfloat16 g_h_hi[M_TOT * DIMN],  g_h_lo[M_TOT * DIMN];
__device__ __nv_bfloat16 g_ao_hi[M_TOT * DIMN], g_ao_lo[M_TOT * DIMN];
__device__ __nv_bfloat16 g_wq_hi[DIMN * DIMN], g_wq_lo[DIMN * DIMN];
__device__ __nv_bfloat16 g_wk_hi[DIMN * DIMN], g_wk_lo[DIMN * DIMN];
__device__ __nv_bfloat16 g_wv_hi[DIMN * DIMN], g_wv_lo[DIMN * DIMN];
__device__ __nv_bfloat16 g_wo_hi[DIMN * DIMN], g_wo_lo[DIMN * DIMN];

// ---------------------------------------------------------------------------
// fp32 -> bf16 hi/lo split (elementwise, float4 per thread)
// ---------------------------------------------------------------------------
__global__ __launch_bounds__(256) void split_kernel(const float* __restrict__ src,
                                                    __nv_bfloat16* __restrict__ hi,
                                                    __nv_bfloat16* __restrict__ lo,
                                                    int n4) {
    int i = blockIdx.x * blockDim.x + threadIdx.x;
    if (i >= n4) return;
    float4 v = ((const float4*)src)[i];
    __nv_bfloat16 h0 = __float2bfloat16(v.x), h1 = __float2bfloat16(v.y);
    __nv_bfloat16 h2 = __float2bfloat16(v.z), h3 = __float2bfloat16(v.w);
    __nv_bfloat16 l0 = __float2bfloat16(v.x - __bfloat162float(h0));
    __nv_bfloat16 l1 = __float2bfloat16(v.y - __bfloat162float(h1));
    __nv_bfloat16 l2 = __float2bfloat16(v.z - __bfloat162float(h2));
    __nv_bfloat16 l3 = __float2bfloat16(v.w - __bfloat162float(h3));
    ushort4 H, L;
    H.x = *(unsigned short*)&h0; H.y = *(unsigned short*)&h1;
    H.z = *(unsigned short*)&h2; H.w = *(unsigned short*)&h3;
    L.x = *(unsigned short*)&l0; L.y = *(unsigned short*)&l1;
    L.z = *(unsigned short*)&l2; L.w = *(unsigned short*)&l3;
    ((ushort4*)hi)[i] = H;
    ((ushort4*)lo)[i] = L;
}

// ---------------------------------------------------------------------------
// bf16x3 tensor-core GEMM-NT: C[m][n] = sum_k A[m][k] * W[n][k]
// Block 128x128, k-tile 16, 256 threads = 8 warps (2m x 4n), warp tile 64x32.
// cp.async double-buffered smem, ldmatrix fragments, mma.m16n8k16.bf16.
// ---------------------------------------------------------------------------
__device__ __forceinline__ void mma_bf16(float* c, const uint32_t* a, const uint32_t* b) {
    asm volatile(
        "mma.sync.aligned.m16n8k16.row.col.f32.bf16.bf16.f32 "
        "{%0,%1,%2,%3}, {%4,%5,%6,%7}, {%8,%9}, {%0,%1,%2,%3};"
        : "+f"(c[0]), "+f"(c[1]), "+f"(c[2]), "+f"(c[3])
        : "r"(a[0]), "r"(a[1]), "r"(a[2]), "r"(a[3]), "r"(b[0]), "r"(b[1]));
}

__device__ __forceinline__ void ldsm4(uint32_t* r, uint32_t addr) {
    asm volatile("ldmatrix.sync.aligned.m8n8.x4.shared.b16 {%0,%1,%2,%3}, [%4];"
                 : "=r"(r[0]), "=r"(r[1]), "=r"(r[2]), "=r"(r[3]) : "r"(addr));
}

__device__ __forceinline__ void cpasync16(uint32_t dst, const void* src) {
    asm volatile("cp.async.cg.shared.global [%0], [%1], 16;" :: "r"(dst), "l"(src));
}

#define KT 16
#define PLANE_BYTES (128 * 32)         // 128 rows x 32B (16 bf16)
#define BUF_BYTES   (4 * PLANE_BYTES)  // Ahi, Alo, Bhi, Blo

__device__ __forceinline__ void gemm_bf16x3_body(const __nv_bfloat16* __restrict__ Ahi,
                                                 const __nv_bfloat16* __restrict__ Alo,
                                                 const __nv_bfloat16* __restrict__ Bhi,
                                                 const __nv_bfloat16* __restrict__ Blo,
                                                 float* __restrict__ Cout) {
    const int K = DIMN, N = DIMN;
    __shared__ __align__(16) uint8_t smem[2 * BUF_BYTES];   // 32 KB
    const uint32_t sbase = (uint32_t)__cvta_generic_to_shared(smem);

    const int t    = threadIdx.x;
    const int warp = t >> 5;
    const int lane = t & 31;
    const int wm   = warp >> 2;      // 0..1
    const int wn   = warp & 3;       // 0..3
    const int m0   = blockIdx.y * 128;
    const int n0   = blockIdx.x * 128;

    // --- copy mapping: thread t owns (row = t>>1, chunk c = t&1) of each plane
    const int crow = t >> 1;
    const int cc   = t & 1;
    const uint32_t cdst = (uint32_t)(crow * 32 + ((cc ^ ((crow >> 2) & 1)) << 4));
    const __nv_bfloat16* srcAh = Ahi + (size_t)(m0 + crow) * K + cc * 8;
    const __nv_bfloat16* srcAl = Alo + (size_t)(m0 + crow) * K + cc * 8;
    const __nv_bfloat16* srcBh = Bhi + (size_t)(n0 + crow) * K + cc * 8;
    const __nv_bfloat16* srcBl = Blo + (size_t)(n0 + crow) * K + cc * 8;

    // --- ldmatrix per-lane offsets (constant across k-tiles)
    uint32_t offA[4], offB[2];
#pragma unroll
    for (int mt = 0; mt < 4; ++mt) {
        int mat  = lane >> 3;
        int row  = wm * 64 + mt * 16 + (mat & 1) * 8 + (lane & 7);
        int cbit = lane >> 4;                       // mat>>1
        offA[mt] = (uint32_t)(row * 32 + ((cbit ^ ((row >> 2) & 1)) << 4));
    }
#pragma unroll
    for (int j2 = 0; j2 < 2; ++j2) {
        int row  = wn * 32 + j2 * 16 + (lane >> 4) * 8 + (lane & 7);  // tile = mat>>1
        int cbit = (lane >> 3) & 1;
        offB[j2] = (uint32_t)(row * 32 + ((cbit ^ ((row >> 2) & 1)) << 4));
    }

    float acc[4][4][4];
#pragma unroll
    for (int i = 0; i < 4; ++i)
#pragma unroll
        for (int j = 0; j < 4; ++j)
#pragma unroll
            for (int r = 0; r < 4; ++r) acc[i][j][r] = 0.f;

    const int NT = K / KT;   // 64

    // prologue: tile 0 -> buffer 0
    {
        uint32_t b0 = sbase;
        cpasync16(b0 + 0 * PLANE_BYTES + cdst, srcAh);
        cpasync16(b0 + 1 * PLANE_BYTES + cdst, srcAl);
        cpasync16(b0 + 2 * PLANE_BYTES + cdst, srcBh);
        cpasync16(b0 + 3 * PLANE_BYTES + cdst, srcBl);
        asm volatile("cp.async.commit_group;");
        asm volatile("cp.async.wait_group 0;");
    }
    __syncthreads();

    int p = 0;
    for (int kt = 0; kt < NT; ++kt) {
        if (kt + 1 < NT) {
            uint32_t bn = sbase + (p ^ 1) * BUF_BYTES;
            const int ko = (kt + 1) * KT;
            cpasync16(bn + 0 * PLANE_BYTES + cdst, srcAh + ko);
            cpasync16(bn + 1 * PLANE_BYTES + cdst, srcAl + ko);
            cpasync16(bn + 2 * PLANE_BYTES + cdst, srcBh + ko);
            cpasync16(bn + 3 * PLANE_BYTES + cdst, srcBl + ko);
            asm volatile("cp.async.commit_group;");
        }

        const uint32_t base = sbase + p * BUF_BYTES;
        uint32_t a_hi[4][4], a_lo[4][4], bf[2][4];
#pragma unroll
        for (int mt = 0; mt < 4; ++mt) ldsm4(a_hi[mt], base + 0 * PLANE_BYTES + offA[mt]);
#pragma unroll
        for (int mt = 0; mt < 4; ++mt) ldsm4(a_lo[mt], base + 1 * PLANE_BYTES + offA[mt]);
#pragma unroll
        for (int j2 = 0; j2 < 2; ++j2) ldsm4(bf[j2], base + 2 * PLANE_BYTES + offB[j2]);

#pragma unroll
        for (int i = 0; i < 4; ++i)
#pragma unroll
            for (int j = 0; j < 4; ++j) mma_bf16(acc[i][j], a_hi[i], &bf[j >> 1][(j & 1) * 2]);
#pragma unroll
        for (int i = 0; i < 4; ++i)
#pragma unroll
            for (int j = 0; j < 4; ++j) mma_bf16(acc[i][j], a_lo[i], &bf[j >> 1][(j & 1) * 2]);

#pragma unroll
        for (int j2 = 0; j2 < 2; ++j2) ldsm4(bf[j2], base + 3 * PLANE_BYTES + offB[j2]);
#pragma unroll
        for (int i = 0; i < 4; ++i)
#pragma unroll
            for (int j = 0; j < 4; ++j) mma_bf16(acc[i][j], a_hi[i], &bf[j >> 1][(j & 1) * 2]);

        if (kt + 1 < NT) {
            asm volatile("cp.async.wait_group 0;");
            __syncthreads();
            p ^= 1;
        }
    }

    // epilogue
    const int g  = lane >> 2;
    const int tg = lane & 3;
#pragma unroll
    for (int i = 0; i < 4; ++i) {
        const int row = m0 + wm * 64 + i * 16 + g;
#pragma unroll
        for (int j = 0; j < 4; ++j) {
            const int col = n0 + wn * 32 + j * 8 + tg * 2;
            *(float2*)(Cout + (size_t)row * N + col)       = make_float2(acc[i][j][0], acc[i][j][1]);
            *(float2*)(Cout + (size_t)(row + 8) * N + col) = make_float2(acc[i][j][2], acc[i][j][3]);
        }
    }
}

__global__ __launch_bounds__(256, 2) void qkv_kernel() {
    const __nv_bfloat16* Wh = (blockIdx.z == 0) ? g_wq_hi : (blockIdx.z == 1) ? g_wk_hi : g_wv_hi;
    const __nv_bfloat16* Wl = (blockIdx.z == 0) ? g_wq_lo : (blockIdx.z == 1) ? g_wk_lo : g_wv_lo;
    float* out = (blockIdx.z == 0) ? g_Q : (blockIdx.z == 1) ? g_K : g_V;
    gemm_bf16x3_body(g_h_hi, g_h_lo, Wh, Wl, out);
}

__global__ __launch_bounds__(256, 2) void proj_kernel(float* __restrict__ out) {
    gemm_bf16x3_body(g_ao_hi, g_ao_lo, g_wo_hi, g_wo_lo, out);
}

// ---------------------------------------------------------------------------
// Fused attention (unchanged): flash-style online softmax.
// ---------------------------------------------------------------------------
#define BQ  64
#define BKT 32

__global__ __launch_bounds__(256) void attn_kernel(const float* __restrict__ log_beta) {
    __shared__ float sQ[BQ][68];
    __shared__ float sK[BKT][68];
    __shared__ float sV[BKT][68];

    const int t    = threadIdx.x;
    const int qt   = blockIdx.x;
    const int hb   = blockIdx.y;
    const int hh   = hb >> 3;
    const int bb   = hb & 7;
    const float beta = expf(log_beta[hh]);
    const int q    = t >> 2;
    const int dq   = t & 3;
    const int d0   = dq << 4;
    const int lane = t & 31;

    {
        const int r = t >> 2;
        const int c = (t & 3) << 4;
        const float* src = g_Q + (size_t)((qt * BQ + r) * B_SZ + bb) * DIMN + hh * HD + c;
#pragma unroll
        for (int j = 0; j < 4; ++j)
            *(float4*)&sQ[r][c + j * 4] = *(const float4*)(src + j * 4);
    }

    float acc[16];
#pragma unroll
    for (int i = 0; i < 16; ++i) acc[i] = 0.f;
    float mrow = -1e30f, lrow = 0.f;

    const int kvr = t >> 3;
    const int kvc = (t & 7) << 3;
    const float* ksrc = g_K + (size_t)(kvr * B_SZ + bb) * DIMN + hh * HD + kvc;
    const float* vsrc = g_V + (size_t)(kvr * B_SZ + bb) * DIMN + hh * HD + kvc;

    for (int k0 = 0; k0 < C_SEQ; k0 += BKT) {
        __syncthreads();
        size_t off = (size_t)k0 * B_SZ * DIMN;
        *(float4*)&sK[kvr][kvc]     = *(const float4*)(ksrc + off);
        *(float4*)&sK[kvr][kvc + 4] = *(const float4*)(ksrc + off + 4);
        *(float4*)&sV[kvr][kvc]     = *(const float4*)(vsrc + off);
        *(float4*)&sV[kvr][kvc + 4] = *(const float4*)(vsrc + off + 4);
        __syncthreads();

        float s[8];
#pragma unroll
        for (int j = 0; j < 8; ++j) s[j] = 0.f;
#pragma unroll
        for (int d4 = 0; d4 < 16; ++d4) {
            float4 qv = *(float4*)&sQ[q][d4 * 4];
#pragma unroll
            for (int j = 0; j < 8; ++j) {
                float4 kv = *(float4*)&sK[dq * 8 + j][d4 * 4];
                s[j] = fmaf(qv.x, kv.x, s[j]);
                s[j] = fmaf(qv.y, kv.y, s[j]);
                s[j] = fmaf(qv.z, kv.z, s[j]);
                s[j] = fmaf(qv.w, kv.w, s[j]);
            }
        }
#pragma unroll
        for (int j = 0; j < 8; ++j) s[j] *= beta;

        float mt = s[0];
#pragma unroll
        for (int j = 1; j < 8; ++j) mt = fmaxf(mt, s[j]);
        mt = fmaxf(mt, __shfl_xor_sync(0xffffffffu, mt, 1));
        mt = fmaxf(mt, __shfl_xor_sync(0xffffffffu, mt, 2));
        float mnew  = fmaxf(mrow, mt);
        float scale = __expf(mrow - mnew);
        float pv[8], lsum = 0.f;
#pragma unroll
        for (int j = 0; j < 8; ++j) { pv[j] = __expf(s[j] - mnew); lsum += pv[j]; }
        lsum += __shfl_xor_sync(0xffffffffu, lsum, 1);
        lsum += __shfl_xor_sync(0xffffffffu, lsum, 2);
        lrow = lrow * scale + lsum;
        mrow = mnew;
#pragma unroll
        for (int i = 0; i < 16; ++i) acc[i] *= scale;

        const int base = lane & ~3;
#pragma unroll
        for (int src = 0; src < 4; ++src) {
#pragma unroll
            for (int j = 0; j < 8; ++j) {
                float pk = __shfl_sync(0xffffffffu, pv[j], base + src);
                int kk = src * 8 + j;
#pragma unroll
                for (int i4 = 0; i4 < 4; ++i4) {
                    float4 vv = *(float4*)&sV[kk][d0 + i4 * 4];
                    acc[i4 * 4 + 0] = fmaf(pk, vv.x, acc[i4 * 4 + 0]);
                    acc[i4 * 4 + 1] = fmaf(pk, vv.y, acc[i4 * 4 + 1]);
                    acc[i4 * 4 + 2] = fmaf(pk, vv.z, acc[i4 * 4 + 2]);
                    acc[i4 * 4 + 3] = fmaf(pk, vv.w, acc[i4 * 4 + 3]);
                }
            }
        }
    }

    float inv = 1.f / lrow;
    float* dst = g_AO + (size_t)((qt * BQ + q) * B_SZ + bb) * DIMN + hh * HD + d0;
#pragma unroll
    for (int i4 = 0; i4 < 4; ++i4) {
        float4 o = make_float4(acc[i4 * 4 + 0] * inv, acc[i4 * 4 + 1] * inv,
                               acc[i4 * 4 + 2] * inv, acc[i4 * 4 + 3] * inv);
        *(float4*)(dst + i4 * 4) = o;
    }
}

// ---------------------------------------------------------------------------
// Bias + LayerNorm, in-place on d_out.
// ---------------------------------------------------------------------------
__global__ __launch_bounds__(256) void ln_kernel(const float* __restrict__ b_o,
                                                 const float* __restrict__ gamma,
                                                 const float* __restrict__ lbeta,
                                                 float* __restrict__ io) {
    __shared__ float red[16];
    const int row = blockIdx.x;
    const int t   = threadIdx.x;
    float* x = io + (size_t)row * DIMN;

    float4 xv = *(float4*)&x[t * 4];
    float4 bv = *(const float4*)&b_o[t * 4];
    xv.x += bv.x; xv.y += bv.y; xv.z += bv.z; xv.w += bv.w;

    float s  = xv.x + xv.y + xv.z + xv.w;
    float ss = xv.x * xv.x + xv.y * xv.y + xv.z * xv.z + xv.w * xv.w;
#pragma unroll
    for (int o = 16; o; o >>= 1) {
        s  += __shfl_xor_sync(0xffffffffu, s, o);
        ss += __shfl_xor_sync(0xffffffffu, ss, o);
    }
    if ((t & 31) == 0) { red[t >> 5] = s; red[8 + (t >> 5)] = ss; }
    __syncthreads();
    float stot = 0.f, sstot = 0.f;
#pragma unroll
    for (int w = 0; w < 8; ++w) { stot += red[w]; sstot += red[8 + w]; }

    const float mean = stot * (1.f / DIMN);
    const float var  = sstot * (1.f / DIMN) - mean * mean;
    const float rstd = rsqrtf(var + 1e-5f);

    float4 gv = *(const float4*)&gamma[t * 4];
    float4 ev = *(const float4*)&lbeta[t * 4];
    float4 o;
    o.x = (xv.x - mean) * rstd * gv.x + ev.x;
    o.y = (xv.y - mean) * rstd * gv.y + ev.y;
    o.z = (xv.z - mean) * rstd * gv.z + ev.z;
    o.w = (xv.w - mean) * rstd * gv.w + ev.w;
    *(float4*)&x[t * 4] = o;
}

// ---------------------------------------------------------------------------
extern "C" void kernel_launch(void* const* d_in, const int* in_sizes, int n_in,
                              void* d_out, int out_size) {
    const float* h        = (const float*)d_in[0];
    const float* Wq       = (const float*)d_in[1];
    const float* Wk       = (const float*)d_in[2];
    const float* Wv       = (const float*)d_in[3];
    const float* Wo       = (const float*)d_in[4];
    const float* b_o      = (const float*)d_in[5];
    const float* log_beta = (const float*)d_in[6];
    const float* gamma    = (const float*)d_in[7];
    const float* lbeta    = (const float*)d_in[8];
    float* out = (float*)d_out;

    __nv_bfloat16 *hhi, *hlo, *aohi, *aolo;
    __nv_bfloat16 *wqh, *wql, *wkh, *wkl, *wvh, *wvl, *woh, *wol;
    float *Qp, *Kp, *Vp, *AOp;
    cudaGetSymbolAddress((void**)&hhi,  g_h_hi);  cudaGetSymbolAddress((void**)&hlo,  g_h_lo);
    cudaGetSymbolAddress((void**)&aohi, g_ao_hi); cudaGetSymbolAddress((void**)&aolo, g_ao_lo);
    cudaGetSymbolAddress((void**)&wqh, g_wq_hi);  cudaGetSymbolAddress((void**)&wql, g_wq_lo);
    cudaGetSymbolAddress((void**)&wkh, g_wk_hi);  cudaGetSymbolAddress((void**)&wkl, g_wk_lo);
    cudaGetSymbolAddress((void**)&wvh, g_wv_hi);  cudaGetSymbolAddress((void**)&wvl, g_wv_lo);
    cudaGetSymbolAddress((void**)&woh, g_wo_hi);  cudaGetSymbolAddress((void**)&wol, g_wo_lo);
    cudaGetSymbolAddress((void**)&Qp, g_Q);  cudaGetSymbolAddress((void**)&Kp, g_K);
    cudaGetSymbolAddress((void**)&Vp, g_V);  cudaGetSymbolAddress((void**)&AOp, g_AO);

    const int nW4 = DIMN * DIMN / 4;      // 262144
    const int nH4 = M_TOT * DIMN / 4;     // 2097152
    split_kernel<<<nH4 / 256, 256>>>(h,  hhi, hlo, nH4);
    split_kernel<<<nW4 / 256, 256>>>(Wq, wqh, wql, nW4);
    split_kernel<<<nW4 / 256, 256>>>(Wk, wkh, wkl, nW4);
    split_kernel<<<nW4 / 256, 256>>>(Wv, wvh, wvl, nW4);
    split_kernel<<<nW4 / 256, 256>>>(Wo, woh, wol, nW4);

    qkv_kernel<<<dim3(DIMN / 128, M_TOT / 128, 3), 256>>>();
    attn_kernel<<<dim3(C_SEQ / BQ, NH * B_SZ), 256>>>(log_beta);
    split_kernel<<<nH4 / 256, 256>>>((const float*)AOp, aohi, aolo, nH4);
    proj_kernel<<<dim3(DIMN / 128, M_TOT / 128), 256>>>(out);
    ln_kernel<<<M_TOT, 256>>>(b_o, gamma, lbeta, out);
}

// round 6
// speedup vs baseline: 7.6033x; 6.5918x over previous
#include <cuda_runtime.h>
#include <cuda_bf16.h>
#include <math.h>
#include <stdint.h>

#define C_SEQ 1024
#define B_SZ  8
#define DIMN  1024
#define NH    16
#define HD    64
#define M_TOT (C_SEQ * B_SZ)   // 8192

// bf16 hi/lo planes (static device allocations are allowed)
__device__ __nv_bfloat16 g_hh[M_TOT * DIMN],  g_hl[M_TOT * DIMN];    // h split, [m][k]
__device__ __nv_bfloat16 g_aoh[M_TOT * DIMN], g_aol[M_TOT * DIMN];   // attn out, [m][k]
// Q/K/V planes in [b][h][c][d] layout
__device__ __nv_bfloat16 g_qh[M_TOT * DIMN], g_ql[M_TOT * DIMN];
__device__ __nv_bfloat16 g_kh[M_TOT * DIMN], g_kl[M_TOT * DIMN];
__device__ __nv_bfloat16 g_vh[M_TOT * DIMN], g_vl[M_TOT * DIMN];
// weight planes [n][k]
__device__ __nv_bfloat16 g_wqh[DIMN * DIMN], g_wql[DIMN * DIMN];
__device__ __nv_bfloat16 g_wkh[DIMN * DIMN], g_wkl[DIMN * DIMN];
__device__ __nv_bfloat16 g_wvh[DIMN * DIMN], g_wvl[DIMN * DIMN];
__device__ __nv_bfloat16 g_woh[DIMN * DIMN], g_wol[DIMN * DIMN];

// ---------------------------------------------------------------------------
// helpers
// ---------------------------------------------------------------------------
__device__ __forceinline__ void mma_bf16(float* c, const uint32_t* a, const uint32_t* b) {
    asm volatile(
        "mma.sync.aligned.m16n8k16.row.col.f32.bf16.bf16.f32 "
        "{%0,%1,%2,%3}, {%4,%5,%6,%7}, {%8,%9}, {%0,%1,%2,%3};"
        : "+f"(c[0]), "+f"(c[1]), "+f"(c[2]), "+f"(c[3])
        : "r"(a[0]), "r"(a[1]), "r"(a[2]), "r"(a[3]), "r"(b[0]), "r"(b[1]));
}
__device__ __forceinline__ void ldsm4(uint32_t* r, uint32_t addr) {
    asm volatile("ldmatrix.sync.aligned.m8n8.x4.shared.b16 {%0,%1,%2,%3}, [%4];"
                 : "=r"(r[0]), "=r"(r[1]), "=r"(r[2]), "=r"(r[3]) : "r"(addr));
}
__device__ __forceinline__ void ldsm4t(uint32_t* r, uint32_t addr) {
    asm volatile("ldmatrix.sync.aligned.m8n8.x4.trans.shared.b16 {%0,%1,%2,%3}, [%4];"
                 : "=r"(r[0]), "=r"(r[1]), "=r"(r[2]), "=r"(r[3]) : "r"(addr));
}
__device__ __forceinline__ void cpasync16(uint32_t dst, const void* src) {
    asm volatile("cp.async.cg.shared.global [%0], [%1], 16;" :: "r"(dst), "l"(src));
}
__device__ __forceinline__ void split_pack(float x, float y, uint32_t& hi, uint32_t& lo) {
    __nv_bfloat16 hx = __float2bfloat16(x), hy = __float2bfloat16(y);
    __nv_bfloat16 lx = __float2bfloat16(x - __bfloat162float(hx));
    __nv_bfloat16 ly = __float2bfloat16(y - __bfloat162float(hy));
    hi = (uint32_t)(*(unsigned short*)&hx) | ((uint32_t)(*(unsigned short*)&hy) << 16);
    lo = (uint32_t)(*(unsigned short*)&lx) | ((uint32_t)(*(unsigned short*)&ly) << 16);
}

// ---------------------------------------------------------------------------
// fp32 -> bf16 hi/lo split
// ---------------------------------------------------------------------------
__global__ __launch_bounds__(256) void split_kernel(const float* __restrict__ src,
                                                    __nv_bfloat16* __restrict__ hi,
                                                    __nv_bfloat16* __restrict__ lo,
                                                    int n4) {
    int i = blockIdx.x * blockDim.x + threadIdx.x;
    if (i >= n4) return;
    float4 v = ((const float4*)src)[i];
    uint32_t h0, l0, h1, l1;
    split_pack(v.x, v.y, h0, l0);
    split_pack(v.z, v.w, h1, l1);
    ((uint2*)hi)[i] = make_uint2(h0, h1);
    ((uint2*)lo)[i] = make_uint2(l0, l1);
}

// ---------------------------------------------------------------------------
// bf16x3 GEMM-NT core (validated in R4): acc[m][n] = sum_k A[m][k]*W[n][k]
// ---------------------------------------------------------------------------
#define KT 16
#define PLANE_BYTES (128 * 32)
#define BUF_BYTES   (4 * PLANE_BYTES)

__device__ __forceinline__ void gemm_core(const __nv_bfloat16* __restrict__ Ahi,
                                          const __nv_bfloat16* __restrict__ Alo,
                                          const __nv_bfloat16* __restrict__ Bhi,
                                          const __nv_bfloat16* __restrict__ Blo,
                                          float acc[4][4][4]) {
    const int K = DIMN;
    __shared__ __align__(16) uint8_t smem[2 * BUF_BYTES];
    const uint32_t sbase = (uint32_t)__cvta_generic_to_shared(smem);

    const int t    = threadIdx.x;
    const int warp = t >> 5;
    const int lane = t & 31;
    const int wm   = warp >> 2;
    const int wn   = warp & 3;
    const int m0   = blockIdx.y * 128;
    const int n0   = blockIdx.x * 128;

    const int crow = t >> 1;
    const int cc   = t & 1;
    const uint32_t cdst = (uint32_t)(crow * 32 + ((cc ^ ((crow >> 2) & 1)) << 4));
    const __nv_bfloat16* srcAh = Ahi + (size_t)(m0 + crow) * K + cc * 8;
    const __nv_bfloat16* srcAl = Alo + (size_t)(m0 + crow) * K + cc * 8;
    const __nv_bfloat16* srcBh = Bhi + (size_t)(n0 + crow) * K + cc * 8;
    const __nv_bfloat16* srcBl = Blo + (size_t)(n0 + crow) * K + cc * 8;

    uint32_t offA[4], offB[2];
#pragma unroll
    for (int mt = 0; mt < 4; ++mt) {
        int row  = wm * 64 + mt * 16 + ((lane >> 3) & 1) * 8 + (lane & 7);
        int cbit = lane >> 4;
        offA[mt] = (uint32_t)(row * 32 + ((cbit ^ ((row >> 2) & 1)) << 4));
    }
#pragma unroll
    for (int j2 = 0; j2 < 2; ++j2) {
        int row  = wn * 32 + j2 * 16 + (lane >> 4) * 8 + (lane & 7);
        int cbit = (lane >> 3) & 1;
        offB[j2] = (uint32_t)(row * 32 + ((cbit ^ ((row >> 2) & 1)) << 4));
    }

#pragma unroll
    for (int i = 0; i < 4; ++i)
#pragma unroll
        for (int j = 0; j < 4; ++j)
#pragma unroll
            for (int r = 0; r < 4; ++r) acc[i][j][r] = 0.f;

    const int NT = K / KT;
    {
        uint32_t b0 = sbase;
        cpasync16(b0 + 0 * PLANE_BYTES + cdst, srcAh);
        cpasync16(b0 + 1 * PLANE_BYTES + cdst, srcAl);
        cpasync16(b0 + 2 * PLANE_BYTES + cdst, srcBh);
        cpasync16(b0 + 3 * PLANE_BYTES + cdst, srcBl);
        asm volatile("cp.async.commit_group;");
        asm volatile("cp.async.wait_group 0;");
    }
    __syncthreads();

    int p = 0;
    for (int kt = 0; kt < NT; ++kt) {
        if (kt + 1 < NT) {
            uint32_t bn = sbase + (p ^ 1) * BUF_BYTES;
            const int ko = (kt + 1) * KT;
            cpasync16(bn + 0 * PLANE_BYTES + cdst, srcAh + ko);
            cpasync16(bn + 1 * PLANE_BYTES + cdst, srcAl + ko);
            cpasync16(bn + 2 * PLANE_BYTES + cdst, srcBh + ko);
            cpasync16(bn + 3 * PLANE_BYTES + cdst, srcBl + ko);
            asm volatile("cp.async.commit_group;");
        }
        const uint32_t base = sbase + p * BUF_BYTES;
        uint32_t a_hi[4][4], a_lo[4][4], bf[2][4];
#pragma unroll
        for (int mt = 0; mt < 4; ++mt) ldsm4(a_hi[mt], base + 0 * PLANE_BYTES + offA[mt]);
#pragma unroll
        for (int mt = 0; mt < 4; ++mt) ldsm4(a_lo[mt], base + 1 * PLANE_BYTES + offA[mt]);
#pragma unroll
        for (int j2 = 0; j2 < 2; ++j2) ldsm4(bf[j2], base + 2 * PLANE_BYTES + offB[j2]);
#pragma unroll
        for (int i = 0; i < 4; ++i)
#pragma unroll
            for (int j = 0; j < 4; ++j) mma_bf16(acc[i][j], a_hi[i], &bf[j >> 1][(j & 1) * 2]);
#pragma unroll
        for (int i = 0; i < 4; ++i)
#pragma unroll
            for (int j = 0; j < 4; ++j) mma_bf16(acc[i][j], a_lo[i], &bf[j >> 1][(j & 1) * 2]);
#pragma unroll
        for (int j2 = 0; j2 < 2; ++j2) ldsm4(bf[j2], base + 3 * PLANE_BYTES + offB[j2]);
#pragma unroll
        for (int i = 0; i < 4; ++i)
#pragma unroll
            for (int j = 0; j < 4; ++j) mma_bf16(acc[i][j], a_hi[i], &bf[j >> 1][(j & 1) * 2]);

        if (kt + 1 < NT) {
            asm volatile("cp.async.wait_group 0;");
            __syncthreads();
            p ^= 1;
        }
    }
}

// QKV: epilogue writes bf16 hi/lo planes in [b][h][c][d] layout
__global__ __launch_bounds__(256, 2) void qkv_kernel() {
    const __nv_bfloat16* Wh = (blockIdx.z == 0) ? g_wqh : (blockIdx.z == 1) ? g_wkh : g_wvh;
    const __nv_bfloat16* Wl = (blockIdx.z == 0) ? g_wql : (blockIdx.z == 1) ? g_wkl : g_wvl;
    __nv_bfloat16* Oh = (blockIdx.z == 0) ? g_qh : (blockIdx.z == 1) ? g_kh : g_vh;
    __nv_bfloat16* Ol = (blockIdx.z == 0) ? g_ql : (blockIdx.z == 1) ? g_kl : g_vl;

    float acc[4][4][4];
    gemm_core(g_hh, g_hl, Wh, Wl, acc);

    const int t = threadIdx.x, warp = t >> 5, lane = t & 31;
    const int wm = warp >> 2, wn = warp & 3;
    const int g = lane >> 2, tg = lane & 3;
    const int m0 = blockIdx.y * 128, n0 = blockIdx.x * 128;
#pragma unroll
    for (int i = 0; i < 4; ++i) {
        const int m = m0 + wm * 64 + i * 16 + g;
        const int c = m >> 3, b = m & 7;
#pragma unroll
        for (int j = 0; j < 4; ++j) {
            const int n = n0 + wn * 32 + j * 8 + tg * 2;
            const int h = n >> 6, d = n & 63;
            size_t e0 = (((size_t)b * 16 + h) * 1024 + c) * 64 + d;
            size_t e1 = e0 + 64;   // row m+8 -> c+1
            uint32_t hi, lo;
            split_pack(acc[i][j][0], acc[i][j][1], hi, lo);
            *(uint32_t*)&Oh[e0] = hi; *(uint32_t*)&Ol[e0] = lo;
            split_pack(acc[i][j][2], acc[i][j][3], hi, lo);
            *(uint32_t*)&Oh[e1] = hi; *(uint32_t*)&Ol[e1] = lo;
        }
    }
}

// Output projection: epilogue writes fp32 to d_out
__global__ __launch_bounds__(256, 2) void proj_kernel(float* __restrict__ out) {
    float acc[4][4][4];
    gemm_core(g_aoh, g_aol, g_woh, g_wol, acc);

    const int t = threadIdx.x, warp = t >> 5, lane = t & 31;
    const int wm = warp >> 2, wn = warp & 3;
    const int g = lane >> 2, tg = lane & 3;
    const int m0 = blockIdx.y * 128, n0 = blockIdx.x * 128;
#pragma unroll
    for (int i = 0; i < 4; ++i) {
        const int row = m0 + wm * 64 + i * 16 + g;
#pragma unroll
        for (int j = 0; j < 4; ++j) {
            const int col = n0 + wn * 32 + j * 8 + tg * 2;
            *(float2*)(out + (size_t)row * DIMN + col)       = make_float2(acc[i][j][0], acc[i][j][1]);
            *(float2*)(out + (size_t)(row + 8) * DIMN + col) = make_float2(acc[i][j][2], acc[i][j][3]);
        }
    }
}

// ---------------------------------------------------------------------------
// Tensor-core flash attention.
// Block: 128 queries x one (b,h). 8 warps; warp owns 16 full rows.
// smem: QH 16K | QL 16K | 2 stages x (KH 8K | KL 8K | VH 8K | VL 8K) = 96KB.
// ---------------------------------------------------------------------------
#define ATT_SMEM (96 * 1024)

__device__ __forceinline__ void load_kv_tile(uint32_t sb, int stage, int kt, int t,
                                             const __nv_bfloat16* Kh, const __nv_bfloat16* Kl,
                                             const __nv_bfloat16* Vh, const __nv_bfloat16* Vl) {
    const int row = t >> 2, q = t & 3;
    const uint32_t base = sb + 32768 + stage * 32768;
    const size_t soff = ((size_t)(kt * 64) + row) * 64;
#pragma unroll
    for (int i = 0; i < 2; ++i) {
        const int gr = 2 * q + i;
        const uint32_t d = (uint32_t)(row * 128 + ((gr ^ (row & 7)) << 4));
        cpasync16(base + 0     + d, Kh + soff + gr * 8);
        cpasync16(base + 8192  + d, Kl + soff + gr * 8);
        cpasync16(base + 16384 + d, Vh + soff + gr * 8);
        cpasync16(base + 24576 + d, Vl + soff + gr * 8);
    }
}

__global__ __launch_bounds__(256, 1) void attn2_kernel(const float* __restrict__ log_beta) {
    extern __shared__ __align__(16) uint8_t asmem[];
    const uint32_t sb = (uint32_t)__cvta_generic_to_shared(asmem);

    const int t = threadIdx.x, lane = t & 31, w = t >> 5;
    const int qt = blockIdx.x;            // 0..7
    const int bh = blockIdx.y;            // b*16+h
    const int hh = bh & 15;
    const int bb = bh >> 4;
    const float beta = expf(log_beta[hh]);

    const size_t pbase = (size_t)bh * C_SEQ * HD;
    const __nv_bfloat16* Qh = g_qh + pbase + (size_t)qt * 128 * 64;
    const __nv_bfloat16* Ql = g_ql + pbase + (size_t)qt * 128 * 64;
    const __nv_bfloat16* Kh = g_kh + pbase;
    const __nv_bfloat16* Kl = g_kl + pbase;
    const __nv_bfloat16* Vh = g_vh + pbase;
    const __nv_bfloat16* Vl = g_vl + pbase;

    // Q tile: thread t -> row t>>1, granules (t&1)*4..+3, both planes
    {
        const int row = t >> 1, h2 = t & 1;
#pragma unroll
        for (int i = 0; i < 4; ++i) {
            const int gr = h2 * 4 + i;
            const uint32_t d = (uint32_t)(row * 128 + ((gr ^ (row & 7)) << 4));
            cpasync16(sb + d,         Qh + (size_t)row * 64 + gr * 8);
            cpasync16(sb + 16384 + d, Ql + (size_t)row * 64 + gr * 8);
        }
        asm volatile("cp.async.commit_group;");
    }
    load_kv_tile(sb, 0, 0, t, Kh, Kl, Vh, Vl);
    asm volatile("cp.async.commit_group;");

    asm volatile("cp.async.wait_group 1;");   // Q ready
    __syncthreads();

    // Q fragments (A-frags, 4 k16 tiles, hi+lo)
    uint32_t qhf[4][4], qlf[4][4];
#pragma unroll
    for (int kf = 0; kf < 4; ++kf) {
        const int row  = w * 16 + ((lane >> 3) & 1) * 8 + (lane & 7);
        const int gran = 2 * kf + (lane >> 4);
        const uint32_t off = (uint32_t)(row * 128 + ((gran ^ (row & 7)) << 4));
        ldsm4(qhf[kf], sb + off);
        ldsm4(qlf[kf], sb + 16384 + off);
    }

    float outA[8][4];
#pragma unroll
    for (int nd = 0; nd < 8; ++nd)
#pragma unroll
        for (int r = 0; r < 4; ++r) outA[nd][r] = 0.f;
    float m0 = -1e30f, m1 = -1e30f, l0 = 0.f, l1 = 0.f;

    for (int kt = 0; kt < 16; ++kt) {
        __syncthreads();   // all warps done with buffer kt-1
        if (kt + 1 < 16) {
            load_kv_tile(sb, (kt + 1) & 1, kt + 1, t, Kh, Kl, Vh, Vl);
            asm volatile("cp.async.commit_group;");
            asm volatile("cp.async.wait_group 1;");
        } else {
            asm volatile("cp.async.wait_group 0;");
        }
        __syncthreads();

        const uint32_t KHb = sb + 32768 + (kt & 1) * 32768;
        const uint32_t KLb = KHb + 8192, VHb = KHb + 16384, VLb = KHb + 24576;

        // ---- S = beta * Q K^T (3-pass bf16)
        float S[8][4];
#pragma unroll
        for (int j = 0; j < 8; ++j)
#pragma unroll
            for (int r = 0; r < 4; ++r) S[j][r] = 0.f;

#pragma unroll
        for (int kf = 0; kf < 4; ++kf) {
            uint32_t khf[4][4], klf[4][4];
#pragma unroll
            for (int np = 0; np < 4; ++np) {
                const int row  = np * 16 + ((lane >> 4) & 1) * 8 + (lane & 7);
                const int gran = 2 * kf + ((lane >> 3) & 1);
                const uint32_t off = (uint32_t)(row * 128 + ((gran ^ (row & 7)) << 4));
                ldsm4(khf[np], KHb + off);
                ldsm4(klf[np], KLb + off);
            }
#pragma unroll
            for (int j = 0; j < 8; ++j) mma_bf16(S[j], qhf[kf], &khf[j >> 1][(j & 1) * 2]);
#pragma unroll
            for (int j = 0; j < 8; ++j) mma_bf16(S[j], qlf[kf], &khf[j >> 1][(j & 1) * 2]);
#pragma unroll
            for (int j = 0; j < 8; ++j) mma_bf16(S[j], qhf[kf], &klf[j >> 1][(j & 1) * 2]);
        }
#pragma unroll
        for (int j = 0; j < 8; ++j)
#pragma unroll
            for (int r = 0; r < 4; ++r) S[j][r] *= beta;

        // ---- online softmax (rows g and g+8; cols spread over tg lanes)
        float mt0 = -1e30f, mt1 = -1e30f;
#pragma unroll
        for (int j = 0; j < 8; ++j) {
            mt0 = fmaxf(mt0, fmaxf(S[j][0], S[j][1]));
            mt1 = fmaxf(mt1, fmaxf(S[j][2], S[j][3]));
        }
        mt0 = fmaxf(mt0, __shfl_xor_sync(0xffffffffu, mt0, 1));
        mt0 = fmaxf(mt0, __shfl_xor_sync(0xffffffffu, mt0, 2));
        mt1 = fmaxf(mt1, __shfl_xor_sync(0xffffffffu, mt1, 1));
        mt1 = fmaxf(mt1, __shfl_xor_sync(0xffffffffu, mt1, 2));
        const float mn0 = fmaxf(m0, mt0), mn1 = fmaxf(m1, mt1);
        const float sc0 = __expf(m0 - mn0), sc1 = __expf(m1 - mn1);

        float P[8][4];
        float ls0 = 0.f, ls1 = 0.f;
#pragma unroll
        for (int j = 0; j < 8; ++j) {
            P[j][0] = __expf(S[j][0] - mn0); P[j][1] = __expf(S[j][1] - mn0);
            P[j][2] = __expf(S[j][2] - mn1); P[j][3] = __expf(S[j][3] - mn1);
            ls0 += P[j][0] + P[j][1];
            ls1 += P[j][2] + P[j][3];
        }
        ls0 += __shfl_xor_sync(0xffffffffu, ls0, 1);
        ls0 += __shfl_xor_sync(0xffffffffu, ls0, 2);
        ls1 += __shfl_xor_sync(0xffffffffu, ls1, 1);
        ls1 += __shfl_xor_sync(0xffffffffu, ls1, 2);
        l0 = l0 * sc0 + ls0;  m0 = mn0;
        l1 = l1 * sc1 + ls1;  m1 = mn1;
#pragma unroll
        for (int nd = 0; nd < 8; ++nd) {
            outA[nd][0] *= sc0; outA[nd][1] *= sc0;
            outA[nd][2] *= sc1; outA[nd][3] *= sc1;
        }

        // ---- P -> A-frags (hi/lo); S-tiles 2j,2j+1 feed k-block j
        uint32_t ph[4][4], pl[4][4];
#pragma unroll
        for (int j = 0; j < 4; ++j) {
            split_pack(P[2 * j][0],     P[2 * j][1],     ph[j][0], pl[j][0]);
            split_pack(P[2 * j][2],     P[2 * j][3],     ph[j][1], pl[j][1]);
            split_pack(P[2 * j + 1][0], P[2 * j + 1][1], ph[j][2], pl[j][2]);
            split_pack(P[2 * j + 1][2], P[2 * j + 1][3], ph[j][3], pl[j][3]);
        }

        // ---- out += P V (3-pass)
#pragma unroll
        for (int j = 0; j < 4; ++j) {
            uint32_t vhf[4][4], vlf[4][4];
#pragma unroll
            for (int np = 0; np < 4; ++np) {
                const int row  = j * 16 + ((lane >> 3) & 1) * 8 + (lane & 7);
                const int gran = 2 * np + ((lane >> 4) & 1);
                const uint32_t off = (uint32_t)(row * 128 + ((gran ^ (row & 7)) << 4));
                ldsm4t(vhf[np], VHb + off);
                ldsm4t(vlf[np], VLb + off);
            }
#pragma unroll
            for (int nd = 0; nd < 8; ++nd) mma_bf16(outA[nd], ph[j], &vhf[nd >> 1][(nd & 1) * 2]);
#pragma unroll
            for (int nd = 0; nd < 8; ++nd) mma_bf16(outA[nd], pl[j], &vhf[nd >> 1][(nd & 1) * 2]);
#pragma unroll
            for (int nd = 0; nd < 8; ++nd) mma_bf16(outA[nd], ph[j], &vlf[nd >> 1][(nd & 1) * 2]);
        }
    }

    // ---- epilogue: AO bf16 hi/lo at [m = c*8+b][h*64+d]
    const float i0 = 1.f / l0, i1 = 1.f / l1;
    const int g = lane >> 2, tg = lane & 3;
    const int c0 = qt * 128 + w * 16 + g;
    const size_t r0 = ((size_t)c0 * 8 + bb) * 1024 + hh * 64;
    const size_t r1 = ((size_t)(c0 + 8) * 8 + bb) * 1024 + hh * 64;
#pragma unroll
    for (int nd = 0; nd < 8; ++nd) {
        const int d = nd * 8 + tg * 2;
        uint32_t hi, lo;
        split_pack(outA[nd][0] * i0, outA[nd][1] * i0, hi, lo);
        *(uint32_t*)&g_aoh[r0 + d] = hi; *(uint32_t*)&g_aol[r0 + d] = lo;
        split_pack(outA[nd][2] * i1, outA[nd][3] * i1, hi, lo);
        *(uint32_t*)&g_aoh[r1 + d] = hi; *(uint32_t*)&g_aol[r1 + d] = lo;
    }
}

// ---------------------------------------------------------------------------
// Bias + LayerNorm, in-place on d_out.
// ---------------------------------------------------------------------------
__global__ __launch_bounds__(256) void ln_kernel(const float* __restrict__ b_o,
                                                 const float* __restrict__ gamma,
                                                 const float* __restrict__ lbeta,
                                                 float* __restrict__ io) {
    __shared__ float red[16];
    const int row = blockIdx.x;
    const int t   = threadIdx.x;
    float* x = io + (size_t)row * DIMN;

    float4 xv = *(float4*)&x[t * 4];
    float4 bv = *(const float4*)&b_o[t * 4];
    xv.x += bv.x; xv.y += bv.y; xv.z += bv.z; xv.w += bv.w;

    float s  = xv.x + xv.y + xv.z + xv.w;
    float ss = xv.x * xv.x + xv.y * xv.y + xv.z * xv.z + xv.w * xv.w;
#pragma unroll
    for (int o = 16; o; o >>= 1) {
        s  += __shfl_xor_sync(0xffffffffu, s, o);
        ss += __shfl_xor_sync(0xffffffffu, ss, o);
    }
    if ((t & 31) == 0) { red[t >> 5] = s; red[8 + (t >> 5)] = ss; }
    __syncthreads();
    float stot = 0.f, sstot = 0.f;
#pragma unroll
    for (int wi = 0; wi < 8; ++wi) { stot += red[wi]; sstot += red[8 + wi]; }

    const float mean = stot * (1.f / DIMN);
    const float var  = sstot * (1.f / DIMN) - mean * mean;
    const float rstd = rsqrtf(var + 1e-5f);

    float4 gv = *(const float4*)&gamma[t * 4];
    float4 ev = *(const float4*)&lbeta[t * 4];
    float4 o;
    o.x = (xv.x - mean) * rstd * gv.x + ev.x;
    o.y = (xv.y - mean) * rstd * gv.y + ev.y;
    o.z = (xv.z - mean) * rstd * gv.z + ev.z;
    o.w = (xv.w - mean) * rstd * gv.w + ev.w;
    *(float4*)&x[t * 4] = o;
}

// ---------------------------------------------------------------------------
extern "C" void kernel_launch(void* const* d_in, const int* in_sizes, int n_in,
                              void* d_out, int out_size) {
    const float* h        = (const float*)d_in[0];
    const float* Wq       = (const float*)d_in[1];
    const float* Wk       = (const float*)d_in[2];
    const float* Wv       = (const float*)d_in[3];
    const float* Wo       = (const float*)d_in[4];
    const float* b_o      = (const float*)d_in[5];
    const float* log_beta = (const float*)d_in[6];
    const float* gamma    = (const float*)d_in[7];
    const float* lbeta    = (const float*)d_in[8];
    float* out = (float*)d_out;

    // Unconditional every call: host-side, idempotent, deterministic.
    cudaFuncSetAttribute(attn2_kernel, cudaFuncAttributeMaxDynamicSharedMemorySize, ATT_SMEM);

    __nv_bfloat16 *hh, *hl, *wqh, *wql, *wkh, *wkl, *wvh, *wvl, *woh, *wol;
    cudaGetSymbolAddress((void**)&hh,  g_hh);  cudaGetSymbolAddress((void**)&hl,  g_hl);
    cudaGetSymbolAddress((void**)&wqh, g_wqh); cudaGetSymbolAddress((void**)&wql, g_wql);
    cudaGetSymbolAddress((void**)&wkh, g_wkh); cudaGetSymbolAddress((void**)&wkl, g_wkl);
    cudaGetSymbolAddress((void**)&wvh, g_wvh); cudaGetSymbolAddress((void**)&wvl, g_wvl);
    cudaGetSymbolAddress((void**)&woh, g_woh); cudaGetSymbolAddress((void**)&wol, g_wol);

    const int nW4 = DIMN * DIMN / 4;
    const int nH4 = M_TOT * DIMN / 4;
    split_kernel<<<nH4 / 256, 256>>>(h,  hh,  hl,  nH4);
    split_kernel<<<nW4 / 256, 256>>>(Wq, wqh, wql, nW4);
    split_kernel<<<nW4 / 256, 256>>>(Wk, wkh, wkl, nW4);
    split_kernel<<<nW4 / 256, 256>>>(Wv, wvh, wvl, nW4);
    split_kernel<<<nW4 / 256, 256>>>(Wo, woh, wol, nW4);

    qkv_kernel<<<dim3(DIMN / 128, M_TOT / 128, 3), 256>>>();
    attn2_kernel<<<dim3(C_SEQ / 128, B_SZ * NH), 256, ATT_SMEM>>>(log_beta);
    proj_kernel<<<dim3(DIMN / 128, M_TOT / 128), 256>>>(out);
    ln_kernel<<<M_TOT, 256>>>(b_o, gamma, lbeta, out);
}